// round 12
// baseline (speedup 1.0000x reference)
#include <cuda_runtime.h>
#include <cuda_fp16.h>
#include <cuda_bf16.h>
#include <cstdint>

#define N_NODES 4096
#define EMB     512
#define N_HEADS 8
#define KSP     128
#define HD      64
#define K_TOT   1536          // logical K of the 3-term bf16 split GEMM
#define K_ROW   1024          // stored row length: [hi | lo] only (dedup)

#define ZROWS   16384         // output rows zero-filled by proj_mma (256MB)

// Projected Q (fp32) and K (fp16). K row = 1KB; head slice = 128B, line-aligned.
__device__ float  g_Q [N_NODES * EMB];
__device__ __half g_Kh[N_NODES * EMB];

// Deduplicated bf16-split operands: [hi | lo], 1024 cols each.
__device__ __align__(16) __nv_bfloat16 g_X2 [N_NODES * K_ROW];
__device__ __align__(16) __nv_bfloat16 g_W2q[EMB * K_ROW];
__device__ __align__(16) __nv_bfloat16 g_W2k[EMB * K_ROW];

// ════════════════ portable PTX helpers (valid at compute_103) ═══════════════
__device__ __forceinline__ uint32_t smem_u32_of(const void* p) {
    uint32_t a;
    asm("{ .reg .u64 t; cvta.to.shared.u64 t, %1; cvt.u32.u64 %0, t; }" : "=r"(a) : "l"(p));
    return a;
}
__device__ __forceinline__ void ldsm_x4(uint32_t* r, uint32_t addr) {
    asm volatile("ldmatrix.sync.aligned.m8n8.x4.shared.b16 {%0,%1,%2,%3}, [%4];"
                 : "=r"(r[0]), "=r"(r[1]), "=r"(r[2]), "=r"(r[3]) : "r"(addr));
}
__device__ __forceinline__ void mma_bf16(float* c, const uint32_t* a, const uint32_t* b) {
    asm volatile(
        "mma.sync.aligned.m16n8k16.row.col.f32.bf16.bf16.f32 "
        "{%0,%1,%2,%3}, {%4,%5,%6,%7}, {%8,%9}, {%0,%1,%2,%3};"
        : "+f"(c[0]), "+f"(c[1]), "+f"(c[2]), "+f"(c[3])
        : "r"(a[0]), "r"(a[1]), "r"(a[2]), "r"(a[3]), "r"(b[0]), "r"(b[1]));
}
__device__ __forceinline__ void cp16(uint32_t saddr, const void* gaddr) {
    asm volatile("cp.async.cg.shared.global [%0], [%1], 16;" :: "r"(saddr), "l"(gaddr));
}
#define CP_COMMIT() asm volatile("cp.async.commit_group;" ::: "memory")
#define CP_WAIT0()  asm volatile("cp.async.wait_group 0;" ::: "memory")
#define CP_WAIT1()  asm volatile("cp.async.wait_group 1;" ::: "memory")

// ---------------------------------------------------------------------------
// Fused bf16 split conversion: every source row -> [hi | lo] (1024 halves).
// ---------------------------------------------------------------------------
__global__ void __launch_bounds__(256)
split_convert_all(const float* __restrict__ X,
                  const float* __restrict__ Wq, const float* __restrict__ Wk)
{
    const int r = blockIdx.x;
    const float* src;
    __nv_bfloat16* dst;
    if (r < N_NODES)            { src = X  + (size_t)r * EMB;                   dst = g_X2  + (size_t)r * K_ROW; }
    else if (r < N_NODES + EMB) { src = Wq + (size_t)(r - N_NODES) * EMB;       dst = g_W2q + (size_t)(r - N_NODES) * K_ROW; }
    else                        { src = Wk + (size_t)(r - N_NODES - EMB) * EMB; dst = g_W2k + (size_t)(r - N_NODES - EMB) * K_ROW; }

    const int c = threadIdx.x * 2;
    float2 v = *(const float2*)(src + c);
    __nv_bfloat16 h0 = __float2bfloat16_rn(v.x);
    __nv_bfloat16 h1 = __float2bfloat16_rn(v.y);
    __nv_bfloat16 l0 = __float2bfloat16_rn(v.x - __bfloat162float(h0));
    __nv_bfloat16 l1 = __float2bfloat16_rn(v.y - __bfloat162float(h1));
    __nv_bfloat162 H = {h0, h1}, L = {l0, l1};
    __nv_bfloat162* d0 = (__nv_bfloat162*)(dst + c);
    d0[0]   = H;
    d0[256] = L;
}

// ---------------------------------------------------------------------------
// HMMA projection GEMM v6 = v5 + output zero-fill offload.
// Each of the 256 CTAs also zero-fills 1MB of the final output (rows
// [0,ZROWS)), 11 bounds-checked STG.128 per thread per mainloop iteration —
// fills proj's idle DRAM-write pipe (was 3% busy) so the scatter kernel can
// skip half its zero-fill.
// ---------------------------------------------------------------------------
#define BKG    64
#define NITER  (K_TOT / BKG)      // 24
#define APAD   72                 // 144B row stride; conflict-free ldsm
#define OP_ST  (128 * APAD * 2)   // 18432B per operand per stage
#define STAGE  (2 * OP_ST)        // 36864B
#define SMEMSZ (2 * STAGE)        // 73728B
#define ZF4_PER_CTA 65536         // 1MB of float4 per CTA

__global__ void __launch_bounds__(256, 2)
proj_mma_kernel(const float* __restrict__ bq, const float* __restrict__ bk,
                float* __restrict__ zout)
{
    extern __shared__ __align__(16) char smem[];
    const uint32_t sbase = smem_u32_of(smem);

    const int t      = threadIdx.x;
    const int wid    = t >> 5;
    const int lane   = t & 31;
    const int warp_m = wid & 3;
    const int warp_n = wid >> 2;
    const int z      = blockIdx.z;
    const int rowBase = blockIdx.y * 128;
    const int colBase = blockIdx.x * 128;

    // zero-fill region for this CTA: 1MB at ctaLinear * 1MB
    const int ctaLinear = (z * gridDim.y + blockIdx.y) * gridDim.x + blockIdx.x;
    float4* zb = (float4*)zout + (size_t)ctaLinear * ZF4_PER_CTA;
    const float4 zero4 = make_float4(0.f, 0.f, 0.f, 0.f);

    const __nv_bfloat16* Asrc = g_X2 + (size_t)rowBase * K_ROW;
    const __nv_bfloat16* Bsrc = (z ? g_W2k : g_W2q) + (size_t)colBase * K_ROW;

    const __nv_bfloat16* gA[4];
    const __nv_bfloat16* gB[4];
    uint32_t sA[2][4], sB[2][4];
    #pragma unroll
    for (int i = 0; i < 4; i++) {
        const int c  = t + i * 256;
        const int r  = c >> 3, cc = c & 7;
        gA[i] = Asrc + (size_t)r * K_ROW + cc * 8;
        gB[i] = Bsrc + (size_t)r * K_ROW + cc * 8;
        const uint32_t off = (uint32_t)(r * APAD + cc * 8) * 2;
        sA[0][i] = sbase + off;             sA[1][i] = sbase + STAGE + off;
        sB[0][i] = sbase + OP_ST + off;     sB[1][i] = sbase + STAGE + OP_ST + off;
    }

    float acc[2][8][4];
    #pragma unroll
    for (int mi = 0; mi < 2; mi++)
        #pragma unroll
        for (int ni = 0; ni < 8; ni++)
            #pragma unroll
            for (int e = 0; e < 4; e++) acc[mi][ni][e] = 0.0f;

    uint32_t aAd[2], bAd[2];
    {
        const uint32_t aoff = ((warp_m * 32 + (lane & 15)) * APAD + (lane >> 4) * 8) * 2;
        const uint32_t boff = ((warp_n * 64 + (lane & 15)) * APAD + (lane >> 4) * 8) * 2;
        aAd[0] = sbase + aoff;           aAd[1] = sbase + STAGE + aoff;
        bAd[0] = sbase + OP_ST + boff;   bAd[1] = sbase + STAGE + OP_ST + boff;
    }

    #pragma unroll
    for (int i = 0; i < 4; i++) { cp16(sA[0][i], gA[i]); cp16(sB[0][i], gB[i]); }
    CP_COMMIT();

    #pragma unroll 1
    for (int it = 0; it < NITER; ++it) {
        const int b = it & 1;
        if (it + 1 < NITER) {
            const int k2  = (it + 1) * BKG;
            const int seg = k2 >> 9, kk = k2 & 511;
            const int kA  = (seg == 1) ? 512 + kk : kk;
            const int kB  = (seg == 2) ? 512 + kk : kk;
            const int nb  = b ^ 1;
            #pragma unroll
            for (int i = 0; i < 4; i++) { cp16(sA[nb][i], gA[i] + kA); cp16(sB[nb][i], gB[i] + kB); }
            CP_COMMIT();
            CP_WAIT1();
        } else {
            CP_WAIT0();
        }
        __syncthreads();

        // zero-fill slice for this iteration (independent write stream)
        #pragma unroll
        for (int j = 0; j < 11; j++) {
            const int idx = (it * 11 + j) * 256 + t;
            if (idx < ZF4_PER_CTA) zb[idx] = zero4;
        }

        #pragma unroll
        for (int ks = 0; ks < 4; ks++) {
            uint32_t a[2][4];
            ldsm_x4(a[0], aAd[b] + ks * 32);
            ldsm_x4(a[1], aAd[b] + 16 * (APAD * 2) + ks * 32);
            uint32_t bf[8][2];
            #pragma unroll
            for (int nb4 = 0; nb4 < 4; nb4++) {
                uint32_t r[4];
                ldsm_x4(r, bAd[b] + nb4 * 16 * (APAD * 2) + ks * 32);
                bf[2 * nb4 + 0][0] = r[0]; bf[2 * nb4 + 0][1] = r[2];
                bf[2 * nb4 + 1][0] = r[1]; bf[2 * nb4 + 1][1] = r[3];
            }
            #pragma unroll
            for (int mi = 0; mi < 2; mi++)
                #pragma unroll
                for (int ni = 0; ni < 8; ni++)
                    mma_bf16(acc[mi][ni], a[mi], bf[ni]);
        }
        __syncthreads();
    }

    const float* bias = z ? bk : bq;
    const int mrow = rowBase + warp_m * 32 + (lane >> 2);
    #pragma unroll
    for (int mi = 0; mi < 2; mi++) {
        #pragma unroll
        for (int ni = 0; ni < 8; ni++) {
            const int gn = colBase + warp_n * 64 + ni * 8 + (lane & 3) * 2;
            const float2 bb = *(const float2*)(bias + gn);
            const int gm0 = mrow + mi * 16;
            if (z == 0) {
                float2 o0 = { acc[mi][ni][0] + bb.x, acc[mi][ni][1] + bb.y };
                float2 o1 = { acc[mi][ni][2] + bb.x, acc[mi][ni][3] + bb.y };
                *(float2*)(g_Q + (size_t)gm0 * EMB + gn)       = o0;
                *(float2*)(g_Q + (size_t)(gm0 + 8) * EMB + gn) = o1;
            } else {
                __half2 o0 = __floats2half2_rn(acc[mi][ni][0] + bb.x, acc[mi][ni][1] + bb.y);
                __half2 o1 = __floats2half2_rn(acc[mi][ni][2] + bb.x, acc[mi][ni][3] + bb.y);
                *(__half2*)(g_Kh + (size_t)gm0 * EMB + gn)       = o0;
                *(__half2*)(g_Kh + (size_t)(gm0 + 8) * EMB + gn) = o1;
            }
        }
    }
}

// ---------------------------------------------------------------------------
// Score + scatter v4: rows [0,ZROWS) arrive pre-zeroed by proj_mma -> skip
// the zero-fill pass. Block index bit-interleaved so zeroing and non-zeroing
// CTAs mix within every wave (steady DRAM-write stream).
// ---------------------------------------------------------------------------
__global__ void __launch_bounds__(256)
scatter_scores_kernel(const int* __restrict__ sidx, float* __restrict__ out)
{
    const int bid = blockIdx.x;
    const int b = (bid >> 1) | ((bid & 1) << 14);   // interleave low/high halves
    const int n = b & (N_NODES - 1);
    const int h = b >> 12;
    const int t = threadIdx.x;

    float* rowp = out + (size_t)b * N_NODES;

    const bool needZero = (b >= ZROWS);
    if (needZero) {
        float4 z = make_float4(0.f, 0.f, 0.f, 0.f);
        float4* op = (float4*)rowp;
        #pragma unroll
        for (int i = 0; i < 4; i++) op[t + i * 256] = z;
    }

    const int warp = t >> 5;
    const int lane = t & 31;
    const int quad = lane >> 3;
    const int sub  = lane & 7;

    const int base = (((h << 12) | n) * KSP) + warp * 16;
    int idxreg = sidx[base + (lane & 15)];

    const float4* qp = (const float4*)(g_Q + (size_t)n * EMB + h * HD);
    float4 qa = qp[sub * 2];
    float4 qb = qp[sub * 2 + 1];

    if (needZero) __syncthreads();   // zero-fill visible before scattered stores

    int  kidx[4];
    uint4 kv[4];
    #pragma unroll
    for (int j = 0; j < 4; j++) {
        kidx[j] = __shfl_sync(0xffffffffu, idxreg, 4 * j + quad);
        kv[j] = *(const uint4*)(g_Kh + (size_t)kidx[j] * EMB + h * HD + sub * 8);
    }

    #pragma unroll
    for (int j = 0; j < 4; j++) {
        float2 f0 = __half22float2(*(const __half2*)&kv[j].x);
        float2 f1 = __half22float2(*(const __half2*)&kv[j].y);
        float2 f2 = __half22float2(*(const __half2*)&kv[j].z);
        float2 f3 = __half22float2(*(const __half2*)&kv[j].w);
        float s;
        s  = qa.x * f0.x + qa.y * f0.y;
        s += qa.z * f1.x + qa.w * f1.y;
        s += qb.x * f2.x + qb.y * f2.y;
        s += qb.z * f3.x + qb.w * f3.y;
        s += __shfl_xor_sync(0xffffffffu, s, 4);
        s += __shfl_xor_sync(0xffffffffu, s, 2);
        s += __shfl_xor_sync(0xffffffffu, s, 1);
        if (sub == 0) rowp[kidx[j]] = s * 0.125f;   // 1/sqrt(64)
    }
}

// ---------------------------------------------------------------------------
extern "C" void kernel_launch(void* const* d_in, const int* in_sizes, int n_in,
                              void* d_out, int out_size)
{
    const float* emb = (const float*)d_in[0];
    const float* Wq  = (const float*)d_in[1];
    const float* bq  = (const float*)d_in[2];
    const float* Wk  = (const float*)d_in[3];
    const float* bk  = (const float*)d_in[4];
    const int*   idx = (const int*)d_in[5];
    float* out = (float*)d_out;

    static int smem_set = 0;
    if (!smem_set) {
        cudaFuncSetAttribute(proj_mma_kernel,
                             cudaFuncAttributeMaxDynamicSharedMemorySize, SMEMSZ);
        smem_set = 1;
    }

    split_convert_all<<<N_NODES + 2 * EMB, 256>>>(emb, Wq, Wk);

    dim3 ggrid(EMB / 128, N_NODES / 128, 2);   // 4 x 32 x 2 = 256 CTAs
    proj_mma_kernel<<<ggrid, 256, SMEMSZ>>>(bq, bk, out);

    scatter_scores_kernel<<<N_HEADS * N_NODES, 256>>>(idx, out);
}

// round 13
// speedup vs baseline: 1.5195x; 1.5195x over previous
#include <cuda_runtime.h>
#include <cuda_fp16.h>
#include <cstdint>

#define N_NODES 4096
#define EMB     512
#define N_HEADS 8
#define KSP     128
#define HD      64

// Projected Q (fp32) and K (fp16). K row = 1KB; head slice = 128B, line-aligned.
__device__ float  g_Q [N_NODES * EMB];
__device__ __half g_Kh[N_NODES * EMB];

// fp16 GEMM operands (direct rounding — no split; error budget analysis in log)
__device__ __align__(16) __half g_Xh [N_NODES * EMB];
__device__ __align__(16) __half g_Wqh[EMB * EMB];
__device__ __align__(16) __half g_Wkh[EMB * EMB];

// ════════════════ portable PTX helpers (valid at compute_103) ═══════════════
__device__ __forceinline__ uint32_t smem_u32_of(const void* p) {
    uint32_t a;
    asm("{ .reg .u64 t; cvta.to.shared.u64 t, %1; cvt.u32.u64 %0, t; }" : "=r"(a) : "l"(p));
    return a;
}
__device__ __forceinline__ void ldsm_x4(uint32_t* r, uint32_t addr) {
    asm volatile("ldmatrix.sync.aligned.m8n8.x4.shared.b16 {%0,%1,%2,%3}, [%4];"
                 : "=r"(r[0]), "=r"(r[1]), "=r"(r[2]), "=r"(r[3]) : "r"(addr));
}
__device__ __forceinline__ void mma_f16(float* c, const uint32_t* a, const uint32_t* b) {
    asm volatile(
        "mma.sync.aligned.m16n8k16.row.col.f32.f16.f16.f32 "
        "{%0,%1,%2,%3}, {%4,%5,%6,%7}, {%8,%9}, {%0,%1,%2,%3};"
        : "+f"(c[0]), "+f"(c[1]), "+f"(c[2]), "+f"(c[3])
        : "r"(a[0]), "r"(a[1]), "r"(a[2]), "r"(a[3]), "r"(b[0]), "r"(b[1]));
}
__device__ __forceinline__ void cp16(uint32_t saddr, const void* gaddr) {
    asm volatile("cp.async.cg.shared.global [%0], [%1], 16;" :: "r"(saddr), "l"(gaddr));
}
#define CP_COMMIT() asm volatile("cp.async.commit_group;" ::: "memory")
#define CP_WAIT0()  asm volatile("cp.async.wait_group 0;" ::: "memory")
#define CP_WAIT1()  asm volatile("cp.async.wait_group 1;" ::: "memory")

// ---------------------------------------------------------------------------
// Fused fp16 conversion: rows [0,4096) X -> g_Xh; [4096,4608) Wq -> g_Wqh;
// [4608,5120) Wk -> g_Wkh. 512 floats per row, 2 per thread.
// ---------------------------------------------------------------------------
__global__ void __launch_bounds__(256)
convert_all(const float* __restrict__ X,
            const float* __restrict__ Wq, const float* __restrict__ Wk)
{
    const int r = blockIdx.x;
    const float* src;
    __half* dst;
    if (r < N_NODES)            { src = X  + (size_t)r * EMB;                   dst = g_Xh  + (size_t)r * EMB; }
    else if (r < N_NODES + EMB) { src = Wq + (size_t)(r - N_NODES) * EMB;       dst = g_Wqh + (size_t)(r - N_NODES) * EMB; }
    else                        { src = Wk + (size_t)(r - N_NODES - EMB) * EMB; dst = g_Wkh + (size_t)(r - N_NODES - EMB) * EMB; }

    const int c = threadIdx.x * 2;
    float2 v = *(const float2*)(src + c);
    *(__half2*)(dst + c) = __floats2half2_rn(v.x, v.y);
}

// ---------------------------------------------------------------------------
// HMMA projection GEMM v7: direct fp16, K=512 (no split).
// CTA 128x128, BK=64, 8 warps 4(M)x2(N) warp tile 32x64 (proven fragments),
// 2-stage cp.async, NITER=8. grid=(4,32,2); z=0 -> g_Q (fp32+bq),
// z=1 -> g_Kh (fp16+bk). fp32 accumulate throughout.
// ---------------------------------------------------------------------------
#define BKG    64
#define NITER  (EMB / BKG)        // 8
#define APAD   72                 // 144B row stride; conflict-free ldsm
#define OP_ST  (128 * APAD * 2)   // 18432B per operand per stage
#define STAGE  (2 * OP_ST)        // 36864B
#define SMEMSZ (2 * STAGE)        // 73728B

__global__ void __launch_bounds__(256, 2)
proj_mma_kernel(const float* __restrict__ bq, const float* __restrict__ bk)
{
    extern __shared__ __align__(16) char smem[];
    const uint32_t sbase = smem_u32_of(smem);

    const int t      = threadIdx.x;
    const int wid    = t >> 5;
    const int lane   = t & 31;
    const int warp_m = wid & 3;   // 4 warps x 32 rows
    const int warp_n = wid >> 2;  // 2 warps x 64 cols
    const int z      = blockIdx.z;
    const int rowBase = blockIdx.y * 128;
    const int colBase = blockIdx.x * 128;

    const __half* Asrc = g_Xh + (size_t)rowBase * EMB;
    const __half* Bsrc = (z ? g_Wkh : g_Wqh) + (size_t)colBase * EMB;

    // gmem<->smem: per operand-stage 128 rows x 8 uint4-chunks = 1024; 4/thread.
    const __half* gA[4];
    const __half* gB[4];
    uint32_t sA[2][4], sB[2][4];
    #pragma unroll
    for (int i = 0; i < 4; i++) {
        const int c  = t + i * 256;
        const int r  = c >> 3, cc = c & 7;
        gA[i] = Asrc + (size_t)r * EMB + cc * 8;
        gB[i] = Bsrc + (size_t)r * EMB + cc * 8;
        const uint32_t off = (uint32_t)(r * APAD + cc * 8) * 2;
        sA[0][i] = sbase + off;             sA[1][i] = sbase + STAGE + off;
        sB[0][i] = sbase + OP_ST + off;     sB[1][i] = sbase + STAGE + OP_ST + off;
    }

    float acc[2][8][4];
    #pragma unroll
    for (int mi = 0; mi < 2; mi++)
        #pragma unroll
        for (int ni = 0; ni < 8; ni++)
            #pragma unroll
            for (int e = 0; e < 4; e++) acc[mi][ni][e] = 0.0f;

    uint32_t aAd[2], bAd[2];
    {
        const uint32_t aoff = ((warp_m * 32 + (lane & 15)) * APAD + (lane >> 4) * 8) * 2;
        const uint32_t boff = ((warp_n * 64 + (lane & 15)) * APAD + (lane >> 4) * 8) * 2;
        aAd[0] = sbase + aoff;           aAd[1] = sbase + STAGE + aoff;
        bAd[0] = sbase + OP_ST + boff;   bAd[1] = sbase + STAGE + OP_ST + boff;
    }

    // prologue: stage 0
    #pragma unroll
    for (int i = 0; i < 4; i++) { cp16(sA[0][i], gA[i]); cp16(sB[0][i], gB[i]); }
    CP_COMMIT();

    #pragma unroll 1
    for (int it = 0; it < NITER; ++it) {
        const int b = it & 1;
        if (it + 1 < NITER) {
            const int k2 = (it + 1) * BKG;
            const int nb = b ^ 1;
            #pragma unroll
            for (int i = 0; i < 4; i++) { cp16(sA[nb][i], gA[i] + k2); cp16(sB[nb][i], gB[i] + k2); }
            CP_COMMIT();
            CP_WAIT1();               // stage it arrived; it+1 in flight
        } else {
            CP_WAIT0();
        }
        __syncthreads();

        #pragma unroll
        for (int ks = 0; ks < 4; ks++) {      // BK=64 = 4 x k16
            uint32_t a[2][4];
            ldsm_x4(a[0], aAd[b] + ks * 32);
            ldsm_x4(a[1], aAd[b] + 16 * (APAD * 2) + ks * 32);
            uint32_t bf[8][2];
            #pragma unroll
            for (int nb4 = 0; nb4 < 4; nb4++) {
                uint32_t r[4];
                ldsm_x4(r, bAd[b] + nb4 * 16 * (APAD * 2) + ks * 32);
                bf[2 * nb4 + 0][0] = r[0]; bf[2 * nb4 + 0][1] = r[2];
                bf[2 * nb4 + 1][0] = r[1]; bf[2 * nb4 + 1][1] = r[3];
            }
            #pragma unroll
            for (int mi = 0; mi < 2; mi++)
                #pragma unroll
                for (int ni = 0; ni < 8; ni++)
                    mma_f16(acc[mi][ni], a[mi], bf[ni]);
        }
        __syncthreads();              // buffer b free before reload
    }

    // Epilogue: d-frag m16n8 -> rows lane/4 (+8), cols (lane&3)*2; add bias.
    const float* bias = z ? bk : bq;
    const int mrow = rowBase + warp_m * 32 + (lane >> 2);
    #pragma unroll
    for (int mi = 0; mi < 2; mi++) {
        #pragma unroll
        for (int ni = 0; ni < 8; ni++) {
            const int gn = colBase + warp_n * 64 + ni * 8 + (lane & 3) * 2;
            const float2 bb = *(const float2*)(bias + gn);
            const int gm0 = mrow + mi * 16;
            if (z == 0) {
                float2 o0 = { acc[mi][ni][0] + bb.x, acc[mi][ni][1] + bb.y };
                float2 o1 = { acc[mi][ni][2] + bb.x, acc[mi][ni][3] + bb.y };
                *(float2*)(g_Q + (size_t)gm0 * EMB + gn)       = o0;
                *(float2*)(g_Q + (size_t)(gm0 + 8) * EMB + gn) = o1;
            } else {
                __half2 o0 = __floats2half2_rn(acc[mi][ni][0] + bb.x, acc[mi][ni][1] + bb.y);
                __half2 o1 = __floats2half2_rn(acc[mi][ni][2] + bb.x, acc[mi][ni][3] + bb.y);
                *(__half2*)(g_Kh + (size_t)gm0 * EMB + gn)       = o0;
                *(__half2*)(g_Kh + (size_t)(gm0 + 8) * EMB + gn) = o1;
            }
        }
    }
}

// ---------------------------------------------------------------------------
// Score + scatter (round-11 version, 101.5us verified): fp16 key gather, one
// 128B line per key, direct GMEM zero-fill + scattered 4B stores. Zero-fill
// and scattered stores stay in the SAME CTA (L2-residency — round-12 lesson).
// ---------------------------------------------------------------------------
__global__ void __launch_bounds__(256)
scatter_scores_kernel(const int* __restrict__ sidx, float* __restrict__ out)
{
    const int b = blockIdx.x;
    const int n = b & (N_NODES - 1);
    const int h = b >> 12;
    const int t = threadIdx.x;

    float* rowp = out + (size_t)b * N_NODES;

    float4 z = make_float4(0.f, 0.f, 0.f, 0.f);
    float4* op = (float4*)rowp;
    #pragma unroll
    for (int i = 0; i < 4; i++) op[t + i * 256] = z;

    const int warp = t >> 5;
    const int lane = t & 31;
    const int quad = lane >> 3;
    const int sub  = lane & 7;

    const int base = (((h << 12) | n) * KSP) + warp * 16;
    int idxreg = sidx[base + (lane & 15)];

    const float4* qp = (const float4*)(g_Q + (size_t)n * EMB + h * HD);
    float4 qa = qp[sub * 2];
    float4 qb = qp[sub * 2 + 1];

    __syncthreads();

    int  kidx[4];
    uint4 kv[4];
    #pragma unroll
    for (int j = 0; j < 4; j++) {
        kidx[j] = __shfl_sync(0xffffffffu, idxreg, 4 * j + quad);
        kv[j] = *(const uint4*)(g_Kh + (size_t)kidx[j] * EMB + h * HD + sub * 8);
    }

    #pragma unroll
    for (int j = 0; j < 4; j++) {
        float2 f0 = __half22float2(*(const __half2*)&kv[j].x);
        float2 f1 = __half22float2(*(const __half2*)&kv[j].y);
        float2 f2 = __half22float2(*(const __half2*)&kv[j].z);
        float2 f3 = __half22float2(*(const __half2*)&kv[j].w);
        float s;
        s  = qa.x * f0.x + qa.y * f0.y;
        s += qa.z * f1.x + qa.w * f1.y;
        s += qb.x * f2.x + qb.y * f2.y;
        s += qb.z * f3.x + qb.w * f3.y;
        s += __shfl_xor_sync(0xffffffffu, s, 4);
        s += __shfl_xor_sync(0xffffffffu, s, 2);
        s += __shfl_xor_sync(0xffffffffu, s, 1);
        if (sub == 0) rowp[kidx[j]] = s * 0.125f;   // 1/sqrt(64)
    }
}

// ---------------------------------------------------------------------------
extern "C" void kernel_launch(void* const* d_in, const int* in_sizes, int n_in,
                              void* d_out, int out_size)
{
    const float* emb = (const float*)d_in[0];
    const float* Wq  = (const float*)d_in[1];
    const float* bq  = (const float*)d_in[2];
    const float* Wk  = (const float*)d_in[3];
    const float* bk  = (const float*)d_in[4];
    const int*   idx = (const int*)d_in[5];
    float* out = (float*)d_out;

    static int smem_set = 0;
    if (!smem_set) {
        cudaFuncSetAttribute(proj_mma_kernel,
                             cudaFuncAttributeMaxDynamicSharedMemorySize, SMEMSZ);
        smem_set = 1;
    }

    convert_all<<<N_NODES + 2 * EMB, 256>>>(emb, Wq, Wk);

    dim3 ggrid(EMB / 128, N_NODES / 128, 2);   // 4 x 32 x 2 = 256 CTAs
    proj_mma_kernel<<<ggrid, 256, SMEMSZ>>>(bq, bk);

    scatter_scores_kernel<<<N_HEADS * N_NODES, 256>>>(idx, out);
}

// round 15
// speedup vs baseline: 1.5372x; 1.0116x over previous
#include <cuda_runtime.h>
#include <cuda_fp16.h>
#include <cstdint>

#define N_NODES 4096
#define EMB     512
#define N_HEADS 8
#define KSP     128
#define HD      64

// Projected Q (fp32) and K (fp16). K row = 1KB; head slice = 128B, line-aligned.
__device__ float  g_Q [N_NODES * EMB];
__device__ __half g_Kh[N_NODES * EMB];

// fp16 GEMM operands (direct rounding — error budget verified: rel_err 4.7e-4)
__device__ __align__(16) __half g_Xh [N_NODES * EMB];
__device__ __align__(16) __half g_Wqh[EMB * EMB];
__device__ __align__(16) __half g_Wkh[EMB * EMB];

// ════════════════ portable PTX helpers (valid at compute_103) ═══════════════
__device__ __forceinline__ uint32_t smem_u32_of(const void* p) {
    uint32_t a;
    asm("{ .reg .u64 t; cvta.to.shared.u64 t, %1; cvt.u32.u64 %0, t; }" : "=r"(a) : "l"(p));
    return a;
}
__device__ __forceinline__ void ldsm_x4(uint32_t* r, uint32_t addr) {
    asm volatile("ldmatrix.sync.aligned.m8n8.x4.shared.b16 {%0,%1,%2,%3}, [%4];"
                 : "=r"(r[0]), "=r"(r[1]), "=r"(r[2]), "=r"(r[3]) : "r"(addr));
}
__device__ __forceinline__ void mma_f16(float* c, const uint32_t* a, const uint32_t* b) {
    asm volatile(
        "mma.sync.aligned.m16n8k16.row.col.f32.f16.f16.f32 "
        "{%0,%1,%2,%3}, {%4,%5,%6,%7}, {%8,%9}, {%0,%1,%2,%3};"
        : "+f"(c[0]), "+f"(c[1]), "+f"(c[2]), "+f"(c[3])
        : "r"(a[0]), "r"(a[1]), "r"(a[2]), "r"(a[3]), "r"(b[0]), "r"(b[1]));
}
__device__ __forceinline__ void cp16(uint32_t saddr, const void* gaddr) {
    asm volatile("cp.async.cg.shared.global [%0], [%1], 16;" :: "r"(saddr), "l"(gaddr));
}
#define CP_COMMIT() asm volatile("cp.async.commit_group;" ::: "memory")
#define CP_WAIT0()  asm volatile("cp.async.wait_group 0;" ::: "memory")
#define CP_WAIT1()  asm volatile("cp.async.wait_group 1;" ::: "memory")

// ---------------------------------------------------------------------------
// Fused fp16 conversion v2 (kept from round 14 — it was correct): 640 blocks
// x 256 threads, 16 floats/thread (two float4 loads + two uint4 stores).
// Linear index space: [0, 2097152) X; then Wq (262144); then Wk.
// ---------------------------------------------------------------------------
#define XELEMS (N_NODES * EMB)      // 2097152
#define WELEMS (EMB * EMB)          // 262144

__global__ void __launch_bounds__(256)
convert_all(const float* __restrict__ X,
            const float* __restrict__ Wq, const float* __restrict__ Wk)
{
    const int base = (blockIdx.x * 256 + threadIdx.x) * 16;   // 16 floats/thread
    const float* src;
    __half* dst;
    int off;
    if (base < XELEMS)               { src = X;  dst = g_Xh;  off = base; }
    else if (base < XELEMS + WELEMS) { src = Wq; dst = g_Wqh; off = base - XELEMS; }
    else                             { src = Wk; dst = g_Wkh; off = base - XELEMS - WELEMS; }

    float4 v0 = *(const float4*)(src + off);
    float4 v1 = *(const float4*)(src + off + 4);
    float4 v2 = *(const float4*)(src + off + 8);
    float4 v3 = *(const float4*)(src + off + 12);
    __half2 h[8];
    h[0] = __floats2half2_rn(v0.x, v0.y); h[1] = __floats2half2_rn(v0.z, v0.w);
    h[2] = __floats2half2_rn(v1.x, v1.y); h[3] = __floats2half2_rn(v1.z, v1.w);
    h[4] = __floats2half2_rn(v2.x, v2.y); h[5] = __floats2half2_rn(v2.z, v2.w);
    h[6] = __floats2half2_rn(v3.x, v3.y); h[7] = __floats2half2_rn(v3.z, v3.w);
    *(uint4*)(dst + off)     = *(uint4*)&h[0];
    *(uint4*)(dst + off + 8) = *(uint4*)&h[4];
}

// ---------------------------------------------------------------------------
// HMMA projection GEMM — EXACT round-13 version (verified at 125.4us).
// Direct fp16, K=512. CTA 128x128, BK=64, 8 warps 4(M)x2(N) warp tile 32x64,
// 2-stage cp.async with the proven 1-deep schedule: prefetch it+1 into the
// OPPOSITE buffer, wait, compute. (Round-14's 2-deep prologue raced: stage
// it+2 shares the parity of stage it -> prefetch overwrote a live buffer.)
// ---------------------------------------------------------------------------
#define BKG    64
#define NITER  (EMB / BKG)        // 8
#define APAD   72                 // 144B row stride; conflict-free ldsm
#define OP_ST  (128 * APAD * 2)   // 18432B per operand per stage
#define STAGE  (2 * OP_ST)        // 36864B
#define SMEMSZ (2 * STAGE)        // 73728B

__global__ void __launch_bounds__(256, 2)
proj_mma_kernel(const float* __restrict__ bq, const float* __restrict__ bk)
{
    extern __shared__ __align__(16) char smem[];
    const uint32_t sbase = smem_u32_of(smem);

    const int t      = threadIdx.x;
    const int wid    = t >> 5;
    const int lane   = t & 31;
    const int warp_m = wid & 3;   // 4 warps x 32 rows
    const int warp_n = wid >> 2;  // 2 warps x 64 cols
    const int z      = blockIdx.z;
    const int rowBase = blockIdx.y * 128;
    const int colBase = blockIdx.x * 128;

    const __half* Asrc = g_Xh + (size_t)rowBase * EMB;
    const __half* Bsrc = (z ? g_Wkh : g_Wqh) + (size_t)colBase * EMB;

    const __half* gA[4];
    const __half* gB[4];
    uint32_t sA[2][4], sB[2][4];
    #pragma unroll
    for (int i = 0; i < 4; i++) {
        const int c  = t + i * 256;
        const int r  = c >> 3, cc = c & 7;
        gA[i] = Asrc + (size_t)r * EMB + cc * 8;
        gB[i] = Bsrc + (size_t)r * EMB + cc * 8;
        const uint32_t off = (uint32_t)(r * APAD + cc * 8) * 2;
        sA[0][i] = sbase + off;             sA[1][i] = sbase + STAGE + off;
        sB[0][i] = sbase + OP_ST + off;     sB[1][i] = sbase + STAGE + OP_ST + off;
    }

    float acc[2][8][4];
    #pragma unroll
    for (int mi = 0; mi < 2; mi++)
        #pragma unroll
        for (int ni = 0; ni < 8; ni++)
            #pragma unroll
            for (int e = 0; e < 4; e++) acc[mi][ni][e] = 0.0f;

    uint32_t aAd[2], bAd[2];
    {
        const uint32_t aoff = ((warp_m * 32 + (lane & 15)) * APAD + (lane >> 4) * 8) * 2;
        const uint32_t boff = ((warp_n * 64 + (lane & 15)) * APAD + (lane >> 4) * 8) * 2;
        aAd[0] = sbase + aoff;           aAd[1] = sbase + STAGE + aoff;
        bAd[0] = sbase + OP_ST + boff;   bAd[1] = sbase + STAGE + OP_ST + boff;
    }

    // prologue: stage 0 only (proven schedule)
    #pragma unroll
    for (int i = 0; i < 4; i++) { cp16(sA[0][i], gA[i]); cp16(sB[0][i], gB[i]); }
    CP_COMMIT();

    #pragma unroll 1
    for (int it = 0; it < NITER; ++it) {
        const int b = it & 1;
        if (it + 1 < NITER) {
            const int k2 = (it + 1) * BKG;
            const int nb = b ^ 1;
            #pragma unroll
            for (int i = 0; i < 4; i++) { cp16(sA[nb][i], gA[i] + k2); cp16(sB[nb][i], gB[i] + k2); }
            CP_COMMIT();
            CP_WAIT1();               // stage it arrived; it+1 in flight
        } else {
            CP_WAIT0();
        }
        __syncthreads();

        #pragma unroll
        for (int ks = 0; ks < 4; ks++) {      // BK=64 = 4 x k16
            uint32_t a[2][4];
            ldsm_x4(a[0], aAd[b] + ks * 32);
            ldsm_x4(a[1], aAd[b] + 16 * (APAD * 2) + ks * 32);
            uint32_t bf[8][2];
            #pragma unroll
            for (int nb4 = 0; nb4 < 4; nb4++) {
                uint32_t r[4];
                ldsm_x4(r, bAd[b] + nb4 * 16 * (APAD * 2) + ks * 32);
                bf[2 * nb4 + 0][0] = r[0]; bf[2 * nb4 + 0][1] = r[2];
                bf[2 * nb4 + 1][0] = r[1]; bf[2 * nb4 + 1][1] = r[3];
            }
            #pragma unroll
            for (int mi = 0; mi < 2; mi++)
                #pragma unroll
                for (int ni = 0; ni < 8; ni++)
                    mma_f16(acc[mi][ni], a[mi], bf[ni]);
        }
        __syncthreads();              // buffer b free before reload
    }

    // Epilogue: d-frag m16n8 -> rows lane/4 (+8), cols (lane&3)*2; add bias.
    const float* bias = z ? bk : bq;
    const int mrow = rowBase + warp_m * 32 + (lane >> 2);
    #pragma unroll
    for (int mi = 0; mi < 2; mi++) {
        #pragma unroll
        for (int ni = 0; ni < 8; ni++) {
            const int gn = colBase + warp_n * 64 + ni * 8 + (lane & 3) * 2;
            const float2 bb = *(const float2*)(bias + gn);
            const int gm0 = mrow + mi * 16;
            if (z == 0) {
                float2 o0 = { acc[mi][ni][0] + bb.x, acc[mi][ni][1] + bb.y };
                float2 o1 = { acc[mi][ni][2] + bb.x, acc[mi][ni][3] + bb.y };
                *(float2*)(g_Q + (size_t)gm0 * EMB + gn)       = o0;
                *(float2*)(g_Q + (size_t)(gm0 + 8) * EMB + gn) = o1;
            } else {
                __half2 o0 = __floats2half2_rn(acc[mi][ni][0] + bb.x, acc[mi][ni][1] + bb.y);
                __half2 o1 = __floats2half2_rn(acc[mi][ni][2] + bb.x, acc[mi][ni][3] + bb.y);
                *(__half2*)(g_Kh + (size_t)gm0 * EMB + gn)       = o0;
                *(__half2*)(g_Kh + (size_t)(gm0 + 8) * EMB + gn) = o1;
            }
        }
    }
}

// ---------------------------------------------------------------------------
// Score + scatter (verified 101.5us; at its L1/DRAM structural floor):
// fp16 key gather (one 128B line per key), direct GMEM zero-fill + scattered
// 4B stores. Zero-fill and scatter stay in the SAME CTA (L2 residency).
// ---------------------------------------------------------------------------
__global__ void __launch_bounds__(256)
scatter_scores_kernel(const int* __restrict__ sidx, float* __restrict__ out)
{
    const int b = blockIdx.x;
    const int n = b & (N_NODES - 1);
    const int h = b >> 12;
    const int t = threadIdx.x;

    float* rowp = out + (size_t)b * N_NODES;

    float4 z = make_float4(0.f, 0.f, 0.f, 0.f);
    float4* op = (float4*)rowp;
    #pragma unroll
    for (int i = 0; i < 4; i++) op[t + i * 256] = z;

    const int warp = t >> 5;
    const int lane = t & 31;
    const int quad = lane >> 3;
    const int sub  = lane & 7;

    const int base = (((h << 12) | n) * KSP) + warp * 16;
    int idxreg = sidx[base + (lane & 15)];

    const float4* qp = (const float4*)(g_Q + (size_t)n * EMB + h * HD);
    float4 qa = qp[sub * 2];
    float4 qb = qp[sub * 2 + 1];

    __syncthreads();

    int  kidx[4];
    uint4 kv[4];
    #pragma unroll
    for (int j = 0; j < 4; j++) {
        kidx[j] = __shfl_sync(0xffffffffu, idxreg, 4 * j + quad);
        kv[j] = *(const uint4*)(g_Kh + (size_t)kidx[j] * EMB + h * HD + sub * 8);
    }

    #pragma unroll
    for (int j = 0; j < 4; j++) {
        float2 f0 = __half22float2(*(const __half2*)&kv[j].x);
        float2 f1 = __half22float2(*(const __half2*)&kv[j].y);
        float2 f2 = __half22float2(*(const __half2*)&kv[j].z);
        float2 f3 = __half22float2(*(const __half2*)&kv[j].w);
        float s;
        s  = qa.x * f0.x + qa.y * f0.y;
        s += qa.z * f1.x + qa.w * f1.y;
        s += qb.x * f2.x + qb.y * f2.y;
        s += qb.z * f3.x + qb.w * f3.y;
        s += __shfl_xor_sync(0xffffffffu, s, 4);
        s += __shfl_xor_sync(0xffffffffu, s, 2);
        s += __shfl_xor_sync(0xffffffffu, s, 1);
        if (sub == 0) rowp[kidx[j]] = s * 0.125f;   // 1/sqrt(64)
    }
}

// ---------------------------------------------------------------------------
extern "C" void kernel_launch(void* const* d_in, const int* in_sizes, int n_in,
                              void* d_out, int out_size)
{
    const float* emb = (const float*)d_in[0];
    const float* Wq  = (const float*)d_in[1];
    const float* bq  = (const float*)d_in[2];
    const float* Wk  = (const float*)d_in[3];
    const float* bk  = (const float*)d_in[4];
    const int*   idx = (const int*)d_in[5];
    float* out = (float*)d_out;

    static int smem_set = 0;
    if (!smem_set) {
        cudaFuncSetAttribute(proj_mma_kernel,
                             cudaFuncAttributeMaxDynamicSharedMemorySize, SMEMSZ);
        smem_set = 1;
    }

    convert_all<<<(XELEMS + 2 * WELEMS) / (256 * 16), 256>>>(emb, Wq, Wk);  // 640 blocks

    dim3 ggrid(EMB / 128, N_NODES / 128, 2);   // 4 x 32 x 2 = 256 CTAs
    proj_mma_kernel<<<ggrid, 256, SMEMSZ>>>(bq, bk);

    scatter_scores_kernel<<<N_HEADS * N_NODES, 256>>>(idx, out);
}